// round 8
// baseline (speedup 1.0000x reference)
#include <cuda_runtime.h>
#include <cstdint>

// query [512,32,256], context [512,2048,256], out [16384,2048] fp32.
#define DD   256
#define RD   2048
#define NT   256      // N-chunk per CTA (pass 1)
#define KT   16       // K tile
#define CPAD 260      // padded transposed C row (conflict-free transpose staging)
#define QPAD 36       // padded Qt row (16B-aligned rows)

#define QT_FLOATS (DD * QPAD)          // 9216
#define U_FLOATS  (2 * KT * CPAD)      // 8320  (also holds 8192-float Q staging)
#define P1_SMEM_BYTES ((QT_FLOATS + U_FLOATS) * 4)   // 70144 B -> 3 CTAs/SM

__device__ __forceinline__ uint64_t pack_dup(float x) {
    uint64_t r;
    asm("mov.b64 %0, {%1, %1};" : "=l"(r) : "f"(x));
    return r;
}
__device__ __forceinline__ void fma2(uint64_t& d, uint64_t a, uint64_t b) {
    asm("fma.rn.f32x2 %0, %1, %2, %0;" : "+l"(d) : "l"(a), "l"(b));
}
__device__ __forceinline__ void unpack2(uint64_t v, float& lo, float& hi) {
    asm("mov.b64 {%0, %1}, %2;" : "=f"(lo), "=f"(hi) : "l"(v));
}

// ===================== Pass 1: scores = Q @ C^T -> out ======================
// CTA: 256 threads, tile 32m x 256n, thread tile 8m x 4n (m-paired f32x2).
// 3 CTAs/SM -> 24 warps/SM = 6 warps/SMSP for latency hiding.
__global__ __launch_bounds__(256, 3)
void gemm_kernel(const float* __restrict__ q,
                 const float* __restrict__ ctx,
                 float* __restrict__ out) {
    extern __shared__ float smem[];
    float* Qt = smem;              // [DD][QPAD] : Qt[k][m]
    float* U  = smem + QT_FLOATS;  // union: Q staging (8192 f) / C double buffer

    const int tid = threadIdx.x;
    const int b   = blockIdx.y;
    const int r0  = blockIdx.x * NT;

    // ---- stage Q [32][256] coalesced into U ----
    {
        const float* qb = q + (size_t)b * 32 * DD;
        #pragma unroll
        for (int it = 0; it < 8; ++it) {
            int i = (tid + 256 * it) * 4;
            *(float4*)(U + i) = *(const float4*)(qb + i);
        }
    }
    __syncthreads();
    // ---- transpose U -> Qt[k][m] (one-time) ----
    #pragma unroll
    for (int it = 0; it < 32; ++it) {
        int idx = tid + 256 * it;          // idx = m*256 + k
        Qt[(idx & 255) * QPAD + (idx >> 8)] = U[idx];
    }
    __syncthreads();

    const int mgrp = tid >> 6;             // 0..3  (whole warp same mgrp -> A broadcast)
    const int m0   = mgrp * 8;
    const int n0   = (tid & 63) * 4;       // 4 contiguous n per thread
    const int half = tid & 1;
    const int rowb = tid >> 1;             // 0..127

    const float* cb = ctx + (size_t)b * RD * DD + (size_t)r0 * DD + half * 4;

    uint64_t acc[16];                      // [4 m-pairs][4 n]
    #pragma unroll
    for (int i = 0; i < 16; ++i) acc[i] = 0ull;

    float4 st[2][2];                       // 16 staged floats/thread
    // prefetch k-tile 0 and stage it into buffer 0
    #pragma unroll
    for (int j = 0; j < 2; ++j)
        #pragma unroll
        for (int c = 0; c < 2; ++c)
            st[j][c] = *(const float4*)(cb + (rowb + 128 * j) * DD + c * 8);
    {
        float* bp = U;
        #pragma unroll
        for (int j = 0; j < 2; ++j) {
            const int n = rowb + 128 * j;
            #pragma unroll
            for (int c = 0; c < 2; ++c) {
                const int kl = half * 4 + c * 8;
                bp[(kl + 0) * CPAD + n] = st[j][c].x;
                bp[(kl + 1) * CPAD + n] = st[j][c].y;
                bp[(kl + 2) * CPAD + n] = st[j][c].z;
                bp[(kl + 3) * CPAD + n] = st[j][c].w;
            }
        }
    }
    __syncthreads();

    for (int kt = 0; kt < DD / KT; ++kt) {
        const float* bp = U + (kt & 1) * (KT * CPAD);
        const bool more = (kt + 1 < DD / KT);

        // prefetch next tile to regs (latency hidden under compute)
        if (more) {
            const float* cn = cb + (kt + 1) * KT;
            #pragma unroll
            for (int j = 0; j < 2; ++j)
                #pragma unroll
                for (int c = 0; c < 2; ++c)
                    st[j][c] = *(const float4*)(cn + (rowb + 128 * j) * DD + c * 8);
        }

        // compute this tile
        const float* aq0 = Qt + kt * KT * QPAD + m0;
        #pragma unroll
        for (int k = 0; k < KT; ++k) {
            const float* aq = aq0 + k * QPAD;
            ulonglong2 A0 = *(const ulonglong2*)(aq);       // m-pairs (m0..m0+3)
            ulonglong2 A1 = *(const ulonglong2*)(aq + 4);   // (m0+4..m0+7)
            float4 bv = *(const float4*)(bp + k * CPAD + n0);
            uint64_t b0 = pack_dup(bv.x), b1 = pack_dup(bv.y);
            uint64_t b2 = pack_dup(bv.z), b3 = pack_dup(bv.w);
            fma2(acc[ 0], A0.x, b0); fma2(acc[ 1], A0.x, b1);
            fma2(acc[ 2], A0.x, b2); fma2(acc[ 3], A0.x, b3);
            fma2(acc[ 4], A0.y, b0); fma2(acc[ 5], A0.y, b1);
            fma2(acc[ 6], A0.y, b2); fma2(acc[ 7], A0.y, b3);
            fma2(acc[ 8], A1.x, b0); fma2(acc[ 9], A1.x, b1);
            fma2(acc[10], A1.x, b2); fma2(acc[11], A1.x, b3);
            fma2(acc[12], A1.y, b0); fma2(acc[13], A1.y, b1);
            fma2(acc[14], A1.y, b2); fma2(acc[15], A1.y, b3);
        }

        // stage next tile into the other buffer, then one barrier
        if (more) {
            float* np = U + ((kt + 1) & 1) * (KT * CPAD);
            #pragma unroll
            for (int j = 0; j < 2; ++j) {
                const int n = rowb + 128 * j;
                #pragma unroll
                for (int c = 0; c < 2; ++c) {
                    const int kl = half * 4 + c * 8;
                    np[(kl + 0) * CPAD + n] = st[j][c].x;
                    np[(kl + 1) * CPAD + n] = st[j][c].y;
                    np[(kl + 2) * CPAD + n] = st[j][c].z;
                    np[(kl + 3) * CPAD + n] = st[j][c].w;
                }
            }
            __syncthreads();
        }
    }

    // ---- epilogue: write scores to gmem (coalesced float4) ----
    float* ob = out + ((size_t)b * 32 + m0) * RD + r0 + n0;
    #pragma unroll
    for (int mp = 0; mp < 4; ++mp) {
        float4 lo, hi;
        unpack2(acc[mp * 4 + 0], lo.x, hi.x);
        unpack2(acc[mp * 4 + 1], lo.y, hi.y);
        unpack2(acc[mp * 4 + 2], lo.z, hi.z);
        unpack2(acc[mp * 4 + 3], lo.w, hi.w);
        *(float4*)(ob + (size_t)(2 * mp)     * RD) = lo;
        *(float4*)(ob + (size_t)(2 * mp + 1) * RD) = hi;
    }
}

// ============ Pass 2: in-place sparsemax, register-resident rows ============
__global__ __launch_bounds__(256)
void sparsemax_kernel(float* __restrict__ out) {
    const int lane = threadIdx.x & 31;
    const size_t row = (size_t)blockIdx.x * 8 + (threadIdx.x >> 5);
    float4* rp = (float4*)(out + row * RD);

    float4 v[16];
    #pragma unroll
    for (int t = 0; t < 16; ++t) v[t] = rp[lane + 32 * t];

    // row max
    float vmax = -1e30f;
    #pragma unroll
    for (int t = 0; t < 16; ++t)
        vmax = fmaxf(vmax, fmaxf(fmaxf(v[t].x, v[t].y), fmaxf(v[t].z, v[t].w)));
    #pragma unroll
    for (int s = 16; s; s >>= 1)
        vmax = fmaxf(vmax, __shfl_xor_sync(0xffffffffu, vmax, s));

    // Newton from below on f(tau) = sum(relu(z - tau)) - 1 (convex PL, monotone)
    float tau = vmax - 1.0f;
    for (int it = 0; it < 48; ++it) {
        float S = 0.0f; int cnt = 0;
        #pragma unroll
        for (int t = 0; t < 16; ++t) {
            float d;
            d = v[t].x - tau; if (d > 0.0f) { S += d; cnt++; }
            d = v[t].y - tau; if (d > 0.0f) { S += d; cnt++; }
            d = v[t].z - tau; if (d > 0.0f) { S += d; cnt++; }
            d = v[t].w - tau; if (d > 0.0f) { S += d; cnt++; }
        }
        #pragma unroll
        for (int s = 16; s; s >>= 1) {
            S   += __shfl_xor_sync(0xffffffffu, S, s);
            cnt += __shfl_xor_sync(0xffffffffu, cnt, s);
        }
        if (cnt == 0) break;
        float delta = (S - 1.0f) / (float)cnt;
        if (!(delta > 1e-7f * fmaxf(fabsf(tau), 1.0f))) break;
        tau += delta;
    }

    #pragma unroll
    for (int t = 0; t < 16; ++t) {
        float4 o;
        o.x = fmaxf(v[t].x - tau, 0.0f);
        o.y = fmaxf(v[t].y - tau, 0.0f);
        o.z = fmaxf(v[t].z - tau, 0.0f);
        o.w = fmaxf(v[t].w - tau, 0.0f);
        rp[lane + 32 * t] = o;
    }
}

extern "C" void kernel_launch(void* const* d_in, const int* in_sizes, int n_in,
                              void* d_out, int out_size) {
    (void)n_in; (void)out_size;
    const float* q   = (const float*)d_in[0];
    const float* ctx = (const float*)d_in[1];
    float* out = (float*)d_out;

    const int B = in_sizes[0] / (32 * DD);   // 512

    cudaFuncSetAttribute(gemm_kernel,
                         cudaFuncAttributeMaxDynamicSharedMemorySize, P1_SMEM_BYTES);

    dim3 g1(RD / NT, B);                     // 8 x 512 CTAs
    gemm_kernel<<<g1, 256, P1_SMEM_BYTES>>>(q, ctx, out);

    const int rows = B * 32;                 // 16384
    sparsemax_kernel<<<rows / 8, 256>>>(out);
}

// round 10
// speedup vs baseline: 1.0585x; 1.0585x over previous
#include <cuda_runtime.h>
#include <cstdint>

// query [512,32,256], context [512,2048,256], out [16384,2048] fp32.
#define DD   256
#define RD   2048
#define NT   256      // N-chunk per CTA (pass 1)
#define KT   16       // K tile
#define CPAD 260      // padded transposed C row (conflict-free transpose staging)
#define QPAD 36       // padded Qt row (16B-aligned rows)

#define QT_FLOATS (DD * QPAD)          // 9216
#define U_FLOATS  (2 * KT * CPAD)      // 8320  (also holds 8192-float Q staging)
#define P1_SMEM_BYTES ((QT_FLOATS + U_FLOATS) * 4)   // 70144 B -> 3 CTAs/SM

__device__ __forceinline__ uint64_t pack_dup(float x) {
    uint64_t r;
    asm("mov.b64 %0, {%1, %1};" : "=l"(r) : "f"(x));
    return r;
}
__device__ __forceinline__ void fma2(uint64_t& d, uint64_t a, uint64_t b) {
    asm("fma.rn.f32x2 %0, %1, %2, %0;" : "+l"(d) : "l"(a), "l"(b));
}
__device__ __forceinline__ void unpack2(uint64_t v, float& lo, float& hi) {
    asm("mov.b64 {%0, %1}, %2;" : "=f"(lo), "=f"(hi) : "l"(v));
}

// ===================== Pass 1: scores = Q @ C^T -> out ======================
// CTA: 128 threads, tile 32m x 256n, thread tile 16m x 4n (m-paired f32x2).
__global__ __launch_bounds__(128, 3)
void gemm_kernel(const float* __restrict__ q,
                 const float* __restrict__ ctx,
                 float* __restrict__ out) {
    extern __shared__ float smem[];
    float* Qt = smem;              // [DD][QPAD] : Qt[k][m]
    float* U  = smem + QT_FLOATS;  // union: Q staging (8192 f) / C double buffer

    const int tid = threadIdx.x;
    const int b   = blockIdx.y;
    const int r0  = blockIdx.x * NT;

    // ---- stage Q [32][256] coalesced into U ----
    {
        const float* qb = q + (size_t)b * 32 * DD;
        #pragma unroll
        for (int it = 0; it < 16; ++it) {
            int i = (tid + 128 * it) * 4;
            *(float4*)(U + i) = *(const float4*)(qb + i);
        }
    }
    __syncthreads();
    // ---- transpose U -> Qt[k][m] (one-time) ----
    #pragma unroll
    for (int it = 0; it < 64; ++it) {
        int idx = tid + 128 * it;          // idx = m*256 + k
        Qt[(idx & 255) * QPAD + (idx >> 8)] = U[idx];
    }
    __syncthreads();

    const int mgrp = tid >> 6;             // 0..1  (whole warp same mgrp -> A broadcast)
    const int m0   = mgrp * 16;
    const int n0   = (tid & 63) * 4;       // 4 contiguous n per thread
    const int half = tid & 1;
    const int rowb = tid >> 1;             // 0..63

    const float* cb = ctx + (size_t)b * RD * DD + (size_t)r0 * DD + half * 4;

    uint64_t acc[32];                      // [8 m-pairs][4 n]
    #pragma unroll
    for (int i = 0; i < 32; ++i) acc[i] = 0ull;

    float4 st[4][2];
    // prefetch k-tile 0 and stage it into buffer 0
    #pragma unroll
    for (int j = 0; j < 4; ++j)
        #pragma unroll
        for (int c = 0; c < 2; ++c)
            st[j][c] = *(const float4*)(cb + (rowb + 64 * j) * DD + c * 8);
    {
        float* bp = U;
        #pragma unroll
        for (int j = 0; j < 4; ++j) {
            const int n = rowb + 64 * j;
            #pragma unroll
            for (int c = 0; c < 2; ++c) {
                const int kl = half * 4 + c * 8;
                bp[(kl + 0) * CPAD + n] = st[j][c].x;
                bp[(kl + 1) * CPAD + n] = st[j][c].y;
                bp[(kl + 2) * CPAD + n] = st[j][c].z;
                bp[(kl + 3) * CPAD + n] = st[j][c].w;
            }
        }
    }
    __syncthreads();

    for (int kt = 0; kt < DD / KT; ++kt) {
        const float* bp = U + (kt & 1) * (KT * CPAD);
        const bool more = (kt + 1 < DD / KT);

        // prefetch next tile to regs (latency hidden under compute)
        if (more) {
            const float* cn = cb + (kt + 1) * KT;
            #pragma unroll
            for (int j = 0; j < 4; ++j)
                #pragma unroll
                for (int c = 0; c < 2; ++c)
                    st[j][c] = *(const float4*)(cn + (rowb + 64 * j) * DD + c * 8);
        }

        // compute this tile
        const float* aq0 = Qt + kt * KT * QPAD + m0;
        #pragma unroll
        for (int k = 0; k < KT; ++k) {
            const float* aq = aq0 + k * QPAD;
            // 16 m-values as 8 f32x2 pairs (broadcast loads, conflict-free)
            ulonglong2 A0 = *(const ulonglong2*)(aq);       // (m0..m0+3)
            ulonglong2 A1 = *(const ulonglong2*)(aq + 4);   // (m0+4..m0+7)
            ulonglong2 A2 = *(const ulonglong2*)(aq + 8);   // (m0+8..m0+11)
            ulonglong2 A3 = *(const ulonglong2*)(aq + 12);  // (m0+12..m0+15)
            float4 bv = *(const float4*)(bp + k * CPAD + n0);
            uint64_t b0 = pack_dup(bv.x), b1 = pack_dup(bv.y);
            uint64_t b2 = pack_dup(bv.z), b3 = pack_dup(bv.w);
            fma2(acc[ 0], A0.x, b0); fma2(acc[ 1], A0.x, b1);
            fma2(acc[ 2], A0.x, b2); fma2(acc[ 3], A0.x, b3);
            fma2(acc[ 4], A0.y, b0); fma2(acc[ 5], A0.y, b1);
            fma2(acc[ 6], A0.y, b2); fma2(acc[ 7], A0.y, b3);
            fma2(acc[ 8], A1.x, b0); fma2(acc[ 9], A1.x, b1);
            fma2(acc[10], A1.x, b2); fma2(acc[11], A1.x, b3);
            fma2(acc[12], A1.y, b0); fma2(acc[13], A1.y, b1);
            fma2(acc[14], A1.y, b2); fma2(acc[15], A1.y, b3);
            fma2(acc[16], A2.x, b0); fma2(acc[17], A2.x, b1);
            fma2(acc[18], A2.x, b2); fma2(acc[19], A2.x, b3);
            fma2(acc[20], A2.y, b0); fma2(acc[21], A2.y, b1);
            fma2(acc[22], A2.y, b2); fma2(acc[23], A2.y, b3);
            fma2(acc[24], A3.x, b0); fma2(acc[25], A3.x, b1);
            fma2(acc[26], A3.x, b2); fma2(acc[27], A3.x, b3);
            fma2(acc[28], A3.y, b0); fma2(acc[29], A3.y, b1);
            fma2(acc[30], A3.y, b2); fma2(acc[31], A3.y, b3);
        }

        // stage next tile into the other buffer, then one barrier
        if (more) {
            float* np = U + ((kt + 1) & 1) * (KT * CPAD);
            #pragma unroll
            for (int j = 0; j < 4; ++j) {
                const int n = rowb + 64 * j;
                #pragma unroll
                for (int c = 0; c < 2; ++c) {
                    const int kl = half * 4 + c * 8;
                    np[(kl + 0) * CPAD + n] = st[j][c].x;
                    np[(kl + 1) * CPAD + n] = st[j][c].y;
                    np[(kl + 2) * CPAD + n] = st[j][c].z;
                    np[(kl + 3) * CPAD + n] = st[j][c].w;
                }
            }
            __syncthreads();
        }
    }

    // ---- epilogue: write scores to gmem (coalesced float4) ----
    float* ob = out + ((size_t)b * 32 + m0) * RD + r0 + n0;
    #pragma unroll
    for (int mp = 0; mp < 8; ++mp) {
        float4 lo, hi;
        unpack2(acc[mp * 4 + 0], lo.x, hi.x);
        unpack2(acc[mp * 4 + 1], lo.y, hi.y);
        unpack2(acc[mp * 4 + 2], lo.z, hi.z);
        unpack2(acc[mp * 4 + 3], lo.w, hi.w);
        *(float4*)(ob + (size_t)(2 * mp)     * RD) = lo;
        *(float4*)(ob + (size_t)(2 * mp + 1) * RD) = hi;
    }
}

// ============ Pass 2: in-place sparsemax, register-resident rows ============
__global__ __launch_bounds__(256)
void sparsemax_kernel(float* __restrict__ out) {
    const int lane = threadIdx.x & 31;
    const size_t row = (size_t)blockIdx.x * 8 + (threadIdx.x >> 5);
    float4* rp = (float4*)(out + row * RD);

    float4 v[16];
    #pragma unroll
    for (int t = 0; t < 16; ++t) v[t] = rp[lane + 32 * t];

    // row max
    float vmax = -1e30f;
    #pragma unroll
    for (int t = 0; t < 16; ++t)
        vmax = fmaxf(vmax, fmaxf(fmaxf(v[t].x, v[t].y), fmaxf(v[t].z, v[t].w)));
    #pragma unroll
    for (int s = 16; s; s >>= 1)
        vmax = fmaxf(vmax, __shfl_xor_sync(0xffffffffu, vmax, s));

    // Newton from below on f(tau) = sum(relu(z - tau)) - 1 (convex PL, monotone)
    float tau = vmax - 1.0f;
    for (int it = 0; it < 48; ++it) {
        float S = 0.0f; int cnt = 0;
        #pragma unroll
        for (int t = 0; t < 16; ++t) {
            float d;
            d = v[t].x - tau; if (d > 0.0f) { S += d; cnt++; }
            d = v[t].y - tau; if (d > 0.0f) { S += d; cnt++; }
            d = v[t].z - tau; if (d > 0.0f) { S += d; cnt++; }
            d = v[t].w - tau; if (d > 0.0f) { S += d; cnt++; }
        }
        #pragma unroll
        for (int s = 16; s; s >>= 1) {
            S   += __shfl_xor_sync(0xffffffffu, S, s);
            cnt += __shfl_xor_sync(0xffffffffu, cnt, s);
        }
        if (cnt == 0) break;
        float delta = (S - 1.0f) / (float)cnt;
        if (!(delta > 1e-7f * fmaxf(fabsf(tau), 1.0f))) break;
        tau += delta;
    }

    #pragma unroll
    for (int t = 0; t < 16; ++t) {
        float4 o;
        o.x = fmaxf(v[t].x - tau, 0.0f);
        o.y = fmaxf(v[t].y - tau, 0.0f);
        o.z = fmaxf(v[t].z - tau, 0.0f);
        o.w = fmaxf(v[t].w - tau, 0.0f);
        rp[lane + 32 * t] = o;
    }
}

// Tiny no-op kernel: padding launches so the per-call launch pattern has
// period 5 (gemm, sparsemax, noop, noop, noop). ncu's -s 5 -c 1 then lands on
// launch index 5 = the FIRST launch of the SECOND kernel_launch call =
// gemm_kernel, giving us a profile of the kernel that owns ~92% of runtime.
__global__ void noop_kernel() {}

extern "C" void kernel_launch(void* const* d_in, const int* in_sizes, int n_in,
                              void* d_out, int out_size) {
    (void)n_in; (void)out_size;
    const float* q   = (const float*)d_in[0];
    const float* ctx = (const float*)d_in[1];
    float* out = (float*)d_out;

    const int B = in_sizes[0] / (32 * DD);   // 512

    cudaFuncSetAttribute(gemm_kernel,
                         cudaFuncAttributeMaxDynamicSharedMemorySize, P1_SMEM_BYTES);

    dim3 g1(RD / NT, B);                     // 8 x 512 CTAs
    gemm_kernel<<<g1, 128, P1_SMEM_BYTES>>>(q, ctx, out);

    const int rows = B * 32;                 // 16384
    sparsemax_kernel<<<rows / 8, 256>>>(out);

    // profiling-alignment padding (graph-capturable, deterministic, ~negligible)
    noop_kernel<<<1, 32>>>();
    noop_kernel<<<1, 32>>>();
    noop_kernel<<<1, 32>>>();
}

// round 12
// speedup vs baseline: 1.0590x; 1.0005x over previous
#include <cuda_runtime.h>
#include <cstdint>

// query [512,32,256], context [512,2048,256], out [16384,2048] fp32.
#define DD   256
#define RD   2048
#define NT   256      // N-chunk per CTA
#define KT   16       // K tile
#define CPAD 260      // padded transposed C row (conflict-free transpose staging)
#define QPAD 36       // padded Qt row (16B-aligned rows)
#define NCHUNKS (RD / NT)   // 8 CTAs per batch

#define QT_FLOATS (DD * QPAD)          // 9216
#define U_FLOATS  (2 * KT * CPAD)      // 8320  (also holds 8192-float Q staging)
#define P1_SMEM_BYTES ((QT_FLOATS + U_FLOATS) * 4)   // 70144 B -> 3 CTAs/SM

// per-batch completion counters (zero-initialized at module load; the last
// arriving CTA resets its counter to 0, so every graph replay starts clean)
__device__ int g_cnt[512];

__device__ __forceinline__ uint64_t pack_dup(float x) {
    uint64_t r;
    asm("mov.b64 %0, {%1, %1};" : "=l"(r) : "f"(x));
    return r;
}
__device__ __forceinline__ void fma2(uint64_t& d, uint64_t a, uint64_t b) {
    asm("fma.rn.f32x2 %0, %1, %2, %0;" : "+l"(d) : "l"(a), "l"(b));
}
__device__ __forceinline__ void unpack2(uint64_t v, float& lo, float& hi) {
    asm("mov.b64 {%0, %1}, %2;" : "=f"(lo), "=f"(hi) : "l"(v));
}

// ============ Fused: scores = Q @ C^T -> out, then sparsemax by last CTA ====
// CTA: 128 threads, tile 32m x 256n, thread tile 16m x 4n (m-paired f32x2).
__global__ __launch_bounds__(128, 3)
void ruleattn_fused(const float* __restrict__ q,
                    const float* __restrict__ ctx,
                    float* __restrict__ out) {
    extern __shared__ float smem[];
    float* Qt = smem;              // [DD][QPAD] : Qt[k][m]
    float* U  = smem + QT_FLOATS;  // union: Q staging (8192 f) / C double buffer
    __shared__ int s_last;

    const int tid = threadIdx.x;
    const int b   = blockIdx.y;
    const int r0  = blockIdx.x * NT;

    // ---- stage Q [32][256] coalesced into U ----
    {
        const float* qb = q + (size_t)b * 32 * DD;
        #pragma unroll
        for (int it = 0; it < 16; ++it) {
            int i = (tid + 128 * it) * 4;
            *(float4*)(U + i) = *(const float4*)(qb + i);
        }
    }
    __syncthreads();
    // ---- transpose U -> Qt[k][m] (one-time) ----
    #pragma unroll
    for (int it = 0; it < 64; ++it) {
        int idx = tid + 128 * it;          // idx = m*256 + k
        Qt[(idx & 255) * QPAD + (idx >> 8)] = U[idx];
    }
    __syncthreads();

    const int mgrp = tid >> 6;             // 0..1  (whole warp same mgrp -> A broadcast)
    const int m0   = mgrp * 16;
    const int n0   = (tid & 63) * 4;       // 4 contiguous n per thread
    const int half = tid & 1;
    const int rowb = tid >> 1;             // 0..63

    const float* cb = ctx + (size_t)b * RD * DD + (size_t)r0 * DD + half * 4;

    uint64_t acc[32];                      // [8 m-pairs][4 n]
    #pragma unroll
    for (int i = 0; i < 32; ++i) acc[i] = 0ull;

    float4 st[4][2];
    // prefetch k-tile 0 and stage it into buffer 0
    #pragma unroll
    for (int j = 0; j < 4; ++j)
        #pragma unroll
        for (int c = 0; c < 2; ++c)
            st[j][c] = *(const float4*)(cb + (rowb + 64 * j) * DD + c * 8);
    {
        float* bp = U;
        #pragma unroll
        for (int j = 0; j < 4; ++j) {
            const int n = rowb + 64 * j;
            #pragma unroll
            for (int c = 0; c < 2; ++c) {
                const int kl = half * 4 + c * 8;
                bp[(kl + 0) * CPAD + n] = st[j][c].x;
                bp[(kl + 1) * CPAD + n] = st[j][c].y;
                bp[(kl + 2) * CPAD + n] = st[j][c].z;
                bp[(kl + 3) * CPAD + n] = st[j][c].w;
            }
        }
    }
    __syncthreads();

    for (int kt = 0; kt < DD / KT; ++kt) {
        const float* bp = U + (kt & 1) * (KT * CPAD);
        const bool more = (kt + 1 < DD / KT);

        // prefetch next tile to regs (latency hidden under compute)
        if (more) {
            const float* cn = cb + (kt + 1) * KT;
            #pragma unroll
            for (int j = 0; j < 4; ++j)
                #pragma unroll
                for (int c = 0; c < 2; ++c)
                    st[j][c] = *(const float4*)(cn + (rowb + 64 * j) * DD + c * 8);
        }

        // compute this tile
        const float* aq0 = Qt + kt * KT * QPAD + m0;
        #pragma unroll
        for (int k = 0; k < KT; ++k) {
            const float* aq = aq0 + k * QPAD;
            ulonglong2 A0 = *(const ulonglong2*)(aq);       // (m0..m0+3)
            ulonglong2 A1 = *(const ulonglong2*)(aq + 4);   // (m0+4..m0+7)
            ulonglong2 A2 = *(const ulonglong2*)(aq + 8);   // (m0+8..m0+11)
            ulonglong2 A3 = *(const ulonglong2*)(aq + 12);  // (m0+12..m0+15)
            float4 bv = *(const float4*)(bp + k * CPAD + n0);
            uint64_t b0 = pack_dup(bv.x), b1 = pack_dup(bv.y);
            uint64_t b2 = pack_dup(bv.z), b3 = pack_dup(bv.w);
            fma2(acc[ 0], A0.x, b0); fma2(acc[ 1], A0.x, b1);
            fma2(acc[ 2], A0.x, b2); fma2(acc[ 3], A0.x, b3);
            fma2(acc[ 4], A0.y, b0); fma2(acc[ 5], A0.y, b1);
            fma2(acc[ 6], A0.y, b2); fma2(acc[ 7], A0.y, b3);
            fma2(acc[ 8], A1.x, b0); fma2(acc[ 9], A1.x, b1);
            fma2(acc[10], A1.x, b2); fma2(acc[11], A1.x, b3);
            fma2(acc[12], A1.y, b0); fma2(acc[13], A1.y, b1);
            fma2(acc[14], A1.y, b2); fma2(acc[15], A1.y, b3);
            fma2(acc[16], A2.x, b0); fma2(acc[17], A2.x, b1);
            fma2(acc[18], A2.x, b2); fma2(acc[19], A2.x, b3);
            fma2(acc[20], A2.y, b0); fma2(acc[21], A2.y, b1);
            fma2(acc[22], A2.y, b2); fma2(acc[23], A2.y, b3);
            fma2(acc[24], A3.x, b0); fma2(acc[25], A3.x, b1);
            fma2(acc[26], A3.x, b2); fma2(acc[27], A3.x, b3);
            fma2(acc[28], A3.y, b0); fma2(acc[29], A3.y, b1);
            fma2(acc[30], A3.y, b2); fma2(acc[31], A3.y, b3);
        }

        // stage next tile into the other buffer, then one barrier
        if (more) {
            float* np = U + ((kt + 1) & 1) * (KT * CPAD);
            #pragma unroll
            for (int j = 0; j < 4; ++j) {
                const int n = rowb + 64 * j;
                #pragma unroll
                for (int c = 0; c < 2; ++c) {
                    const int kl = half * 4 + c * 8;
                    np[(kl + 0) * CPAD + n] = st[j][c].x;
                    np[(kl + 1) * CPAD + n] = st[j][c].y;
                    np[(kl + 2) * CPAD + n] = st[j][c].z;
                    np[(kl + 3) * CPAD + n] = st[j][c].w;
                }
            }
            __syncthreads();
        }
    }

    // ---- epilogue: write scores to gmem (coalesced float4) ----
    float* ob = out + ((size_t)b * 32 + m0) * RD + r0 + n0;
    #pragma unroll
    for (int mp = 0; mp < 8; ++mp) {
        float4 lo, hi;
        unpack2(acc[mp * 4 + 0], lo.x, hi.x);
        unpack2(acc[mp * 4 + 1], lo.y, hi.y);
        unpack2(acc[mp * 4 + 2], lo.z, hi.z);
        unpack2(acc[mp * 4 + 3], lo.w, hi.w);
        *(float4*)(ob + (size_t)(2 * mp)     * RD) = lo;
        *(float4*)(ob + (size_t)(2 * mp + 1) * RD) = hi;
    }

    // ---- completion protocol: last CTA of this batch runs sparsemax ----
    __threadfence();                 // make this thread's STGs visible device-wide
    __syncthreads();                 // all threads' stores fenced
    if (tid == 0) {
        int old = atomicAdd(&g_cnt[b], 1);
        if (old == NCHUNKS - 1) {
            g_cnt[b] = 0;            // self-reset for next replay
            s_last = 1;
        } else {
            s_last = 0;
        }
    }
    __syncthreads();
    if (!s_last) return;

    __threadfence();                 // acquire: order counter read before loads

    // ---- sparsemax for all 32 rows of batch b (scores hot in L2) ----
    const int w    = tid >> 5;
    const int lane = tid & 31;
    for (int p = 0; p < 8; ++p) {
        const int m = w * 8 + p;
        float4* rp = (float4*)(out + ((size_t)b * 32 + m) * RD);

        float4 v[16];
        #pragma unroll
        for (int t = 0; t < 16; ++t) v[t] = rp[lane + 32 * t];

        // row max
        float vmax = -1e30f;
        #pragma unroll
        for (int t = 0; t < 16; ++t)
            vmax = fmaxf(vmax, fmaxf(fmaxf(v[t].x, v[t].y), fmaxf(v[t].z, v[t].w)));
        #pragma unroll
        for (int s = 16; s; s >>= 1)
            vmax = fmaxf(vmax, __shfl_xor_sync(0xffffffffu, vmax, s));

        // Newton from below on f(tau)=sum(relu(z-tau))-1 (convex PL, monotone)
        float tau = vmax - 1.0f;
        for (int it = 0; it < 48; ++it) {
            float S = 0.0f; int cnt = 0;
            #pragma unroll
            for (int t = 0; t < 16; ++t) {
                float d;
                d = v[t].x - tau; if (d > 0.0f) { S += d; cnt++; }
                d = v[t].y - tau; if (d > 0.0f) { S += d; cnt++; }
                d = v[t].z - tau; if (d > 0.0f) { S += d; cnt++; }
                d = v[t].w - tau; if (d > 0.0f) { S += d; cnt++; }
            }
            #pragma unroll
            for (int s = 16; s; s >>= 1) {
                S   += __shfl_xor_sync(0xffffffffu, S, s);
                cnt += __shfl_xor_sync(0xffffffffu, cnt, s);
            }
            if (cnt == 0) break;
            float delta = (S - 1.0f) / (float)cnt;
            if (!(delta > 1e-7f * fmaxf(fabsf(tau), 1.0f))) break;
            tau += delta;
        }

        #pragma unroll
        for (int t = 0; t < 16; ++t) {
            float4 o;
            o.x = fmaxf(v[t].x - tau, 0.0f);
            o.y = fmaxf(v[t].y - tau, 0.0f);
            o.z = fmaxf(v[t].z - tau, 0.0f);
            o.w = fmaxf(v[t].w - tau, 0.0f);
            rp[lane + 32 * t] = o;
        }
    }
}

extern "C" void kernel_launch(void* const* d_in, const int* in_sizes, int n_in,
                              void* d_out, int out_size) {
    (void)n_in; (void)out_size;
    const float* q   = (const float*)d_in[0];
    const float* ctx = (const float*)d_in[1];
    float* out = (float*)d_out;

    const int B = in_sizes[0] / (32 * DD);   // 512

    cudaFuncSetAttribute(ruleattn_fused,
                         cudaFuncAttributeMaxDynamicSharedMemorySize, P1_SMEM_BYTES);

    dim3 g1(NCHUNKS, B);                     // 8 x 512 CTAs
    ruleattn_fused<<<g1, 128, P1_SMEM_BYTES>>>(q, ctx, out);
}

// round 13
// speedup vs baseline: 1.2949x; 1.2227x over previous
#include <cuda_runtime.h>
#include <cstdint>

// query [512,32,256], context [512,2048,256], out [16384,2048] fp32.
#define DD   256
#define RD   2048
#define NT   256           // N-chunk per CTA
#define KT   32            // k-tile (k-major rows)
#define NKT  (DD / KT)     // 8
#define CSTR 36            // C tile row stride (floats): 32 + 4 pad
#define QSTR 36            // Qt row stride
#define NCHUNKS (RD / NT)  // 8 CTAs per batch

#define QT_FLOATS (DD * QSTR)            // 9216
#define CT_FLOATS (NT * CSTR)            // 9216 per buffer
#define SMEM_FLOATS (QT_FLOATS + 2 * CT_FLOATS)
#define SMEM_BYTES  (SMEM_FLOATS * 4)    // 110592 B -> 2 CTAs/SM

// per-batch completion counters (zero-init at load; last CTA resets -> replay-safe)
__device__ int g_cnt[512];

__device__ __forceinline__ uint64_t pack_dup(float x) {
    uint64_t r;
    asm("mov.b64 %0, {%1, %1};" : "=l"(r) : "f"(x));
    return r;
}
__device__ __forceinline__ void fma2(uint64_t& d, uint64_t a, uint64_t b) {
    asm("fma.rn.f32x2 %0, %1, %2, %0;" : "+l"(d) : "l"(a), "l"(b));
}
__device__ __forceinline__ void unpack2(uint64_t v, float& lo, float& hi) {
    asm("mov.b64 {%0, %1}, %2;" : "=f"(lo), "=f"(hi) : "l"(v));
}
__device__ __forceinline__ void cp16(uint32_t dst, const float* src) {
    asm volatile("cp.async.cg.shared.global [%0], [%1], 16;" :: "r"(dst), "l"(src));
}
#define CP_COMMIT()  asm volatile("cp.async.commit_group;" ::: "memory")
#define CP_WAIT1()   asm volatile("cp.async.wait_group 1;" ::: "memory")

// ============ Fused: scores = Q @ C^T -> out, then sparsemax by last CTA ====
// CTA: 128 threads, tile 32m x 256n, thread tile 16m x 4n (m-paired f32x2).
__global__ __launch_bounds__(128, 2)
void ruleattn_fused(const float* __restrict__ q,
                    const float* __restrict__ ctx,
                    float* __restrict__ out) {
    extern __shared__ float smem[];
    float* Qt  = smem;                    // [256 k][QSTR] : Qt[k][m], m<32
    float* Cb0 = smem + QT_FLOATS;        // C tile buffer 0 (k-major swizzled)
    float* Cb1 = Cb0 + CT_FLOATS;         // C tile buffer 1
    __shared__ int s_last;

    const uint32_t sbase = (uint32_t)__cvta_generic_to_shared(smem);

    const int tid = threadIdx.x;
    const int b   = blockIdx.y;
    const int r0  = blockIdx.x * NT;

    // ---- stage Q [32][256] coalesced into Cb0 (reused before main loop) ----
    {
        const float* qb = q + (size_t)b * 32 * DD;
        #pragma unroll
        for (int it = 0; it < 16; ++it) {
            int i = (tid + 128 * it) * 4;
            *(float4*)(Cb0 + i) = *(const float4*)(qb + i);
        }
    }
    __syncthreads();
    // ---- transpose Cb0 -> Qt[k][m] (one-time; 4-way conflicts acceptable) ----
    #pragma unroll
    for (int it = 0; it < 64; ++it) {
        int idx = tid + 128 * it;          // idx = m*256 + k
        Qt[(idx & 255) * QSTR + (idx >> 8)] = Cb0[idx];
    }
    __syncthreads();

    const float* cb = ctx + (size_t)b * RD * DD + (size_t)r0 * DD;  // [256][256]

    // issue one k-tile copy: C[r0..r0+255][kt*32 .. +32) -> swizzled k-major smem
    auto issue_tile = [&](int kt, const float* buf) {
        uint32_t dstb = sbase + (uint32_t)((buf - smem) * 4);
        #pragma unroll
        for (int i = 0; i < 16; ++i) {
            int f   = i * 128 + tid;       // float4 index in tile (2048 total)
            int row = f >> 3;              // 8 float4 per row
            int c   = f & 7;
            const float* src = cb + row * DD + kt * KT + c * 4;
            uint32_t dst = dstb + (uint32_t)((row * CSTR + ((c ^ ((row >> 2) & 7)) * 4)) * 4);
            cp16(dst, src);
        }
        CP_COMMIT();
    };

    issue_tile(0, Cb0);
    issue_tile(1, Cb1);

    const int mgrp = tid >> 6;             // 0..1 (whole warp same mgrp -> A broadcast)
    const int m0   = mgrp * 16;
    const int nsl  = tid & 63;             // n slot
    const int n0   = nsl * 4;
    const int sw   = nsl & 7;              // B swizzle key ((n0>>2)&7)

    uint64_t acc[32];                      // [8 m-pairs][4 n]
    #pragma unroll
    for (int i = 0; i < 32; ++i) acc[i] = 0ull;

    for (int kt = 0; kt < NKT; ++kt) {
        CP_WAIT1();                        // tile kt resident (<=1 pending group)
        __syncthreads();
        const float* bp  = (kt & 1) ? Cb1 : Cb0;
        const float* aqt = Qt + kt * KT * QSTR + m0;

        #pragma unroll
        for (int c = 0; c < 8; ++c) {      // 4-k blocks
            // B block: 4 rows x float4 (conflict-free via swizzle)
            const int cc = (c ^ sw) * 4;
            float4 bq0 = *(const float4*)(bp + (n0 + 0) * CSTR + cc);
            float4 bq1 = *(const float4*)(bp + (n0 + 1) * CSTR + cc);
            float4 bq2 = *(const float4*)(bp + (n0 + 2) * CSTR + cc);
            float4 bq3 = *(const float4*)(bp + (n0 + 3) * CSTR + cc);

            #pragma unroll
            for (int kk = 0; kk < 4; ++kk) {
                const float* aq = aqt + (c * 4 + kk) * QSTR;
                ulonglong2 A0 = *(const ulonglong2*)(aq);       // m-pairs (m0..m0+3)
                ulonglong2 A1 = *(const ulonglong2*)(aq + 4);   // (m0+4..m0+7)
                ulonglong2 A2 = *(const ulonglong2*)(aq + 8);   // (m0+8..m0+11)
                ulonglong2 A3 = *(const ulonglong2*)(aq + 12);  // (m0+12..m0+15)
                const float* f0 = &bq0.x; const float* f1 = &bq1.x;
                const float* f2 = &bq2.x; const float* f3 = &bq3.x;
                uint64_t b0 = pack_dup(f0[kk]);
                uint64_t b1 = pack_dup(f1[kk]);
                uint64_t b2 = pack_dup(f2[kk]);
                uint64_t b3 = pack_dup(f3[kk]);
                fma2(acc[ 0], A0.x, b0); fma2(acc[ 1], A0.x, b1);
                fma2(acc[ 2], A0.x, b2); fma2(acc[ 3], A0.x, b3);
                fma2(acc[ 4], A0.y, b0); fma2(acc[ 5], A0.y, b1);
                fma2(acc[ 6], A0.y, b2); fma2(acc[ 7], A0.y, b3);
                fma2(acc[ 8], A1.x, b0); fma2(acc[ 9], A1.x, b1);
                fma2(acc[10], A1.x, b2); fma2(acc[11], A1.x, b3);
                fma2(acc[12], A1.y, b0); fma2(acc[13], A1.y, b1);
                fma2(acc[14], A1.y, b2); fma2(acc[15], A1.y, b3);
                fma2(acc[16], A2.x, b0); fma2(acc[17], A2.x, b1);
                fma2(acc[18], A2.x, b2); fma2(acc[19], A2.x, b3);
                fma2(acc[20], A2.y, b0); fma2(acc[21], A2.y, b1);
                fma2(acc[22], A2.y, b2); fma2(acc[23], A2.y, b3);
                fma2(acc[24], A3.x, b0); fma2(acc[25], A3.x, b1);
                fma2(acc[26], A3.x, b2); fma2(acc[27], A3.x, b3);
                fma2(acc[28], A3.y, b0); fma2(acc[29], A3.y, b1);
                fma2(acc[30], A3.y, b2); fma2(acc[31], A3.y, b3);
            }
        }

        __syncthreads();                   // everyone done reading buf[kt&1]
        if (kt + 2 < NKT) issue_tile(kt + 2, (kt & 1) ? Cb1 : Cb0);
        else              CP_COMMIT();     // empty group keeps wait_group accounting
    }

    // ---- epilogue: write scores to gmem (coalesced float4) ----
    float* ob = out + ((size_t)b * 32 + m0) * RD + r0 + n0;
    #pragma unroll
    for (int mp = 0; mp < 8; ++mp) {
        float4 lo, hi;
        unpack2(acc[mp * 4 + 0], lo.x, hi.x);
        unpack2(acc[mp * 4 + 1], lo.y, hi.y);
        unpack2(acc[mp * 4 + 2], lo.z, hi.z);
        unpack2(acc[mp * 4 + 3], lo.w, hi.w);
        *(float4*)(ob + (size_t)(2 * mp)     * RD) = lo;
        *(float4*)(ob + (size_t)(2 * mp + 1) * RD) = hi;
    }

    // ---- completion protocol: last CTA of this batch runs sparsemax ----
    __threadfence();
    __syncthreads();
    if (tid == 0) {
        int old = atomicAdd(&g_cnt[b], 1);
        if (old == NCHUNKS - 1) { g_cnt[b] = 0; s_last = 1; }
        else                    { s_last = 0; }
    }
    __syncthreads();
    if (!s_last) return;

    __threadfence();                       // acquire

    // ---- sparsemax for all 32 rows of batch b (scores hot in L2) ----
    const int w    = tid >> 5;
    const int lane = tid & 31;
    for (int p = 0; p < 8; ++p) {
        const int m = w * 8 + p;
        float4* rp = (float4*)(out + ((size_t)b * 32 + m) * RD);

        float4 v[16];
        #pragma unroll
        for (int t = 0; t < 16; ++t) v[t] = rp[lane + 32 * t];

        float vmax = -1e30f;
        #pragma unroll
        for (int t = 0; t < 16; ++t)
            vmax = fmaxf(vmax, fmaxf(fmaxf(v[t].x, v[t].y), fmaxf(v[t].z, v[t].w)));
        #pragma unroll
        for (int s = 16; s; s >>= 1)
            vmax = fmaxf(vmax, __shfl_xor_sync(0xffffffffu, vmax, s));

        // Newton from below on f(tau)=sum(relu(z-tau))-1 (convex PL, monotone)
        float tau = vmax - 1.0f;
        for (int it = 0; it < 48; ++it) {
            float S = 0.0f; int cnt = 0;
            #pragma unroll
            for (int t = 0; t < 16; ++t) {
                float d;
                d = v[t].x - tau; if (d > 0.0f) { S += d; cnt++; }
                d = v[t].y - tau; if (d > 0.0f) { S += d; cnt++; }
                d = v[t].z - tau; if (d > 0.0f) { S += d; cnt++; }
                d = v[t].w - tau; if (d > 0.0f) { S += d; cnt++; }
            }
            #pragma unroll
            for (int s = 16; s; s >>= 1) {
                S   += __shfl_xor_sync(0xffffffffu, S, s);
                cnt += __shfl_xor_sync(0xffffffffu, cnt, s);
            }
            if (cnt == 0) break;
            float delta = (S - 1.0f) / (float)cnt;
            if (!(delta > 1e-7f * fmaxf(fabsf(tau), 1.0f))) break;
            tau += delta;
        }

        #pragma unroll
        for (int t = 0; t < 16; ++t) {
            float4 o;
            o.x = fmaxf(v[t].x - tau, 0.0f);
            o.y = fmaxf(v[t].y - tau, 0.0f);
            o.z = fmaxf(v[t].z - tau, 0.0f);
            o.w = fmaxf(v[t].w - tau, 0.0f);
            rp[lane + 32 * t] = o;
        }
    }
}

extern "C" void kernel_launch(void* const* d_in, const int* in_sizes, int n_in,
                              void* d_out, int out_size) {
    (void)n_in; (void)out_size;
    const float* q   = (const float*)d_in[0];
    const float* ctx = (const float*)d_in[1];
    float* out = (float*)d_out;

    const int B = in_sizes[0] / (32 * DD);   // 512

    cudaFuncSetAttribute(ruleattn_fused,
                         cudaFuncAttributeMaxDynamicSharedMemorySize, SMEM_BYTES);

    dim3 g1(NCHUNKS, B);                     // 8 x 512 CTAs
    ruleattn_fused<<<g1, 128, SMEM_BYTES>>>(q, ctx, out);
}